// round 6
// baseline (speedup 1.0000x reference)
#include <cuda_runtime.h>
#include <math.h>

#define BB   8
#define NN   2048
#define DD   256
#define EE   16
#define HH   8
#define CAPC 256
#define NTOK (BB*NN)
#define EB   128

// ------------------------- device scratch (no allocs; zero-initialized) ----------
__device__ int   d_idx1[NTOK];
__device__ int   d_idx2[NTOK];
__device__ float d_g1[NTOK];
__device__ float d_g2[NTOK];
__device__ float d_probsum[BB*EE];      // zero at load; re-zeroed each run by k_combine
__device__ int   d_count1[BB*EE];       // zero at load; re-zeroed each run by k_combine
__device__ float d_U[EB*HH*DD];         // per-(e,b) q projected through Wkv_k
__device__ float d_py[EB*4*HH*DD];      // per-quarter partial y
__device__ float d_pm[EB*4*HH];         // per-quarter softmax max
__device__ float d_ps[EB*4*HH];         // per-quarter softmax sum
__device__ float d_gates[EB*DD];

// ============ K1: gating (warp per token) + qU (blocks 0..127) ============
__global__ void __launch_bounds__(256) k_gate_qU(
    const float* __restrict__ x, const float* __restrict__ audio,
    const float* __restrict__ wg, const float* __restrict__ Wq,
    const float* __restrict__ Wkv)
{
    __shared__ float sprob[EE];
    __shared__ int   scnt[EE];
    __shared__ float sa[DD];
    __shared__ float sq[DD];

    int tid = threadIdx.x, lane = tid & 31, warp = tid >> 5;
    if (tid < EE) { sprob[tid] = 0.f; scnt[tid] = 0; }
    __syncthreads();

    int token = blockIdx.x * 8 + warp;
    {
        const float4* xr4 = (const float4*)(x + (size_t)token * DD);
        float4 xa = xr4[lane], xb = xr4[lane + 32];
        float p[EE];
#pragma unroll
        for (int e = 0; e < EE; e++) p[e] = 0.f;
        const float4* wg4 = (const float4*)wg;     // wg[d][e], row = 4 float4
#pragma unroll
        for (int j = 0; j < 4; j++) {
            float xv = (j==0)?xa.x:(j==1)?xa.y:(j==2)?xa.z:xa.w;
            int d = 4*lane + j;
            float4 w0 = wg4[d*4+0], w1 = wg4[d*4+1], w2 = wg4[d*4+2], w3 = wg4[d*4+3];
            p[0]+=xv*w0.x; p[1]+=xv*w0.y; p[2]+=xv*w0.z; p[3]+=xv*w0.w;
            p[4]+=xv*w1.x; p[5]+=xv*w1.y; p[6]+=xv*w1.z; p[7]+=xv*w1.w;
            p[8]+=xv*w2.x; p[9]+=xv*w2.y; p[10]+=xv*w2.z; p[11]+=xv*w2.w;
            p[12]+=xv*w3.x; p[13]+=xv*w3.y; p[14]+=xv*w3.z; p[15]+=xv*w3.w;
        }
#pragma unroll
        for (int j = 0; j < 4; j++) {
            float xv = (j==0)?xb.x:(j==1)?xb.y:(j==2)?xb.z:xb.w;
            int d = 4*(lane+32) + j;
            float4 w0 = wg4[d*4+0], w1 = wg4[d*4+1], w2 = wg4[d*4+2], w3 = wg4[d*4+3];
            p[0]+=xv*w0.x; p[1]+=xv*w0.y; p[2]+=xv*w0.z; p[3]+=xv*w0.w;
            p[4]+=xv*w1.x; p[5]+=xv*w1.y; p[6]+=xv*w1.z; p[7]+=xv*w1.w;
            p[8]+=xv*w2.x; p[9]+=xv*w2.y; p[10]+=xv*w2.z; p[11]+=xv*w2.w;
            p[12]+=xv*w3.x; p[13]+=xv*w3.y; p[14]+=xv*w3.z; p[15]+=xv*w3.w;
        }
#pragma unroll
        for (int e = 0; e < EE; e++) {
#pragma unroll
            for (int off = 16; off > 0; off >>= 1)
                p[e] += __shfl_xor_sync(0xffffffffu, p[e], off);
        }
        // softmax over 16
        float mx = p[0];
#pragma unroll
        for (int e = 1; e < EE; e++) mx = fmaxf(mx, p[e]);
        float s = 0.f;
#pragma unroll
        for (int e = 0; e < EE; e++) { p[e] = expf(p[e] - mx); s += p[e]; }
        float inv = 1.f / s;
#pragma unroll
        for (int e = 0; e < EE; e++) p[e] *= inv;
        // top-1 / top-2 (first-max tie break)
        int i1 = 0; float g1v = p[0];
#pragma unroll
        for (int e = 1; e < EE; e++) if (p[e] > g1v) { g1v = p[e]; i1 = e; }
        int i2 = (i1 == 0) ? 1 : 0; float g2v = p[i2];
#pragma unroll
        for (int e = 0; e < EE; e++)
            if (e != i1 && p[e] > g2v) { g2v = p[e]; i2 = e; }
        float denom = g1v + g2v + 1e-9f;
        if (lane == 0) {
            d_idx1[token] = i1; d_idx2[token] = i2;
            d_g1[token] = g1v / denom; d_g2[token] = g2v / denom;
            atomicAdd(&scnt[i1], 1);
        }
        if (lane < EE) atomicAdd(&sprob[lane], p[lane]);
    }
    __syncthreads();
    if (tid < EE) {
        int b = (blockIdx.x * 8) >> 11;
        atomicAdd(&d_probsum[b*EE + tid], sprob[tid]);
        atomicAdd(&d_count1[b*EE + tid], scnt[tid]);
    }

    // ---- qU for blocks 0..127 (eb = blockIdx.x) ----
    if (blockIdx.x < EB) {
        int e = blockIdx.x >> 3, b2 = blockIdx.x & 7;
        if (tid < DD) sa[tid] = audio[b2*DD + tid];
        __syncthreads();
        const float* Wqe = Wq + (size_t)e*DD*DD;
        float a0=0.f, a1=0.f, a2=0.f, a3=0.f;
        for (int d = 0; d < DD; d += 4) {
            a0 += sa[d  ] * Wqe[(d  )*DD + tid];
            a1 += sa[d+1] * Wqe[(d+1)*DD + tid];
            a2 += sa[d+2] * Wqe[(d+2)*DD + tid];
            a3 += sa[d+3] * Wqe[(d+3)*DD + tid];
        }
        sq[tid] = a0 + a1 + a2 + a3;
        __syncthreads();
        const float* Wkve = Wkv + (size_t)e*DD*2*DD;
        float qv = sq[warp*32 + lane];
        float* Urow = d_U + ((size_t)blockIdx.x*HH + warp)*DD;
        for (int d = 0; d < DD; d++) {
            float v = Wkve[(size_t)d*512 + warp*32 + lane] * qv;
#pragma unroll
            for (int off = 16; off > 0; off >>= 1)
                v += __shfl_xor_sync(0xffffffffu, v, off);
            if (lane == 0) Urow[d] = v;
        }
    }
}

// ===== K2: positions (recomputed per quarter) + logits + partial softmax + partial y =====
__global__ void __launch_bounds__(256) k_poslogy(const float* __restrict__ x) {
    __shared__ int   s_slots[CAPC];
    __shared__ float sU[HH*DD];
    __shared__ float satt[HH][64];
    __shared__ float sm[HH], ss[HH];
    __shared__ int   wsum[9];
    __shared__ int   s_base;

    int ebq = blockIdx.x;
    int eb = ebq >> 2, qtr = ebq & 3;
    int e = eb >> 3, b = eb & 7;
    int tid = threadIdx.x, lane = tid & 31, warp = tid >> 5;

    s_slots[tid] = -1;
#pragma unroll
    for (int k = 0; k < 8; k++)
        sU[k*256 + tid] = d_U[(size_t)eb*2048 + k*256 + tid];

    // ---- capacity scan (full, recomputed) ----
    int t0 = tid * 8;
    int4 a0 = *(const int4*)(d_idx1 + b*NN + t0);
    int4 a1 = *(const int4*)(d_idx1 + b*NN + t0 + 4);
    int4 c0 = *(const int4*)(d_idx2 + b*NN + t0);
    int4 c1 = *(const int4*)(d_idx2 + b*NN + t0 + 4);
    __syncthreads();
    for (int pass = 0; pass < 2; pass++) {
        int mtch[8];
        if (pass == 0) {
            mtch[0]=(a0.x==e); mtch[1]=(a0.y==e); mtch[2]=(a0.z==e); mtch[3]=(a0.w==e);
            mtch[4]=(a1.x==e); mtch[5]=(a1.y==e); mtch[6]=(a1.z==e); mtch[7]=(a1.w==e);
        } else {
            mtch[0]=(c0.x==e); mtch[1]=(c0.y==e); mtch[2]=(c0.z==e); mtch[3]=(c0.w==e);
            mtch[4]=(c1.x==e); mtch[5]=(c1.y==e); mtch[6]=(c1.z==e); mtch[7]=(c1.w==e);
        }
        int cnt = 0;
#pragma unroll
        for (int k = 0; k < 8; k++) cnt += mtch[k];
        int incl = cnt;
#pragma unroll
        for (int off = 1; off < 32; off <<= 1) {
            int v = __shfl_up_sync(0xffffffffu, incl, off);
            if (lane >= off) incl += v;
        }
        int excl = incl - cnt;
        if (lane == 31) wsum[warp] = incl;
        __syncthreads();
        if (tid == 0) {
            int run = 0;
            for (int w = 0; w < 8; w++) { int t = wsum[w]; wsum[w] = run; run += t; }
            if (pass == 0) s_base = (run < CAPC) ? run : CAPC;
        }
        __syncthreads();
        int base = excl + wsum[warp] + ((pass == 1) ? s_base : 0);
#pragma unroll
        for (int k = 0; k < 8; k++) {
            if (mtch[k]) {
                int n = t0 + k;
                if (base < CAPC) {
                    s_slots[base] = n;
                } else if (qtr == 0) {
                    if (pass == 0) d_g1[b*NN + n] = 0.f;
                    else           d_g2[b*NN + n] = 0.f;
                }
                base++;
            }
        }
        __syncthreads();
    }

    // ---- logits for this quarter's 64 slots (warp handles 8) ----
    const float scale = 0.17677669529663687f;   // 32^-0.5
#pragma unroll
    for (int ci = 0; ci < 8; ci++) {
        int c = warp*8 + ci;
        int tok = s_slots[qtr*64 + c];
        float part[HH];
        if (tok >= 0) {
            const float4* xr4 = (const float4*)(x + ((size_t)b*NN + tok)*DD);
            float4 xa = xr4[lane], xb = xr4[lane + 32];
#pragma unroll
            for (int h = 0; h < HH; h++) {
                const float4* u4 = (const float4*)(sU + h*256);
                float4 ua = u4[lane], ub = u4[lane + 32];
                part[h] = xa.x*ua.x + xa.y*ua.y + xa.z*ua.z + xa.w*ua.w
                        + xb.x*ub.x + xb.y*ub.y + xb.z*ub.z + xb.w*ub.w;
            }
        } else {
#pragma unroll
            for (int h = 0; h < HH; h++) part[h] = 0.f;
        }
#pragma unroll
        for (int h = 0; h < HH; h++) {
            float v = part[h];
#pragma unroll
            for (int off = 16; off > 0; off >>= 1)
                v += __shfl_xor_sync(0xffffffffu, v, off);
            if (lane == 0) satt[h][c] = (tok >= 0) ? v * scale : 0.f;
        }
    }
    __syncthreads();

    // ---- per-quarter online-softmax partial (warp h handles head h, 64 vals) ----
    if (warp < HH) {
        float v0 = satt[warp][lane], v1 = satt[warp][lane + 32];
        float mx = fmaxf(v0, v1);
#pragma unroll
        for (int off = 16; off > 0; off >>= 1)
            mx = fmaxf(mx, __shfl_xor_sync(0xffffffffu, mx, off));
        float e0 = expf(v0 - mx), e1 = expf(v1 - mx);
        float s = e0 + e1;
#pragma unroll
        for (int off = 16; off > 0; off >>= 1)
            s += __shfl_xor_sync(0xffffffffu, s, off);
        satt[warp][lane] = e0; satt[warp][lane + 32] = e1;
        if (lane == 0) { sm[warp] = mx; ss[warp] = s; }
    }
    __syncthreads();

    // ---- partial y over 64 slots (thread = d) ----
    float yv[HH];
#pragma unroll
    for (int h = 0; h < HH; h++) yv[h] = 0.f;
    for (int ci = 0; ci < 64; ci++) {
        int tok = s_slots[qtr*64 + ci];
        if (tok >= 0) {
            float xv = x[((size_t)b*NN + tok)*DD + tid];
#pragma unroll
            for (int h = 0; h < HH; h++) yv[h] += satt[h][ci] * xv;
        }
    }
#pragma unroll
    for (int h = 0; h < HH; h++)
        d_py[(size_t)ebq*2048 + h*256 + tid] = yv[h];
    if (tid < HH) { d_pm[ebq*8 + tid] = sm[tid]; d_ps[ebq*8 + tid] = ss[tid]; }
}

// ============ K3: merge partials + o-projection + sigmoid gate ============
__global__ void __launch_bounds__(256) k_finish(
    const float* __restrict__ Wkv, const float* __restrict__ Wp,
    const float* __restrict__ bp)
{
    __shared__ float sY[HH][DD];
    __shared__ float sO[DD];
    __shared__ float sw[4][HH];
    __shared__ float sSinv[HH];

    int eb = blockIdx.x;
    int e = eb >> 3;
    int tid = threadIdx.x;

    if (tid < HH) {
        float m0 = d_pm[(eb*4+0)*8 + tid], m1 = d_pm[(eb*4+1)*8 + tid];
        float m2 = d_pm[(eb*4+2)*8 + tid], m3 = d_pm[(eb*4+3)*8 + tid];
        float M = fmaxf(fmaxf(m0, m1), fmaxf(m2, m3));
        float w0 = expf(m0 - M), w1 = expf(m1 - M), w2 = expf(m2 - M), w3 = expf(m3 - M);
        float S = w0*d_ps[(eb*4+0)*8 + tid] + w1*d_ps[(eb*4+1)*8 + tid]
                + w2*d_ps[(eb*4+2)*8 + tid] + w3*d_ps[(eb*4+3)*8 + tid];
        sw[0][tid] = w0; sw[1][tid] = w1; sw[2][tid] = w2; sw[3][tid] = w3;
        sSinv[tid] = 1.f / S;
    }
    __syncthreads();

#pragma unroll
    for (int h = 0; h < HH; h++) {
        float y = d_py[(size_t)(eb*4+0)*2048 + h*256 + tid] * sw[0][h]
                + d_py[(size_t)(eb*4+1)*2048 + h*256 + tid] * sw[1][h]
                + d_py[(size_t)(eb*4+2)*2048 + h*256 + tid] * sw[2][h]
                + d_py[(size_t)(eb*4+3)*2048 + h*256 + tid] * sw[3][h];
        sY[h][tid] = y * sSinv[h];
    }
    __syncthreads();

    // o[j] = sum_d y[h(j)][d] * Wkv_v[e][d][256+j]
    const float* Wkve = Wkv + (size_t)e*DD*2*DD;
    {
        int h = tid >> 5;
        float a0=0.f, a1=0.f, a2=0.f, a3=0.f;
        for (int d = 0; d < DD; d += 4) {
            a0 += sY[h][d  ] * Wkve[(size_t)(d  )*512 + 256 + tid];
            a1 += sY[h][d+1] * Wkve[(size_t)(d+1)*512 + 256 + tid];
            a2 += sY[h][d+2] * Wkve[(size_t)(d+2)*512 + 256 + tid];
            a3 += sY[h][d+3] * Wkve[(size_t)(d+3)*512 + 256 + tid];
        }
        sO[tid] = a0 + a1 + a2 + a3;
    }
    __syncthreads();

    // gate[d] = sigmoid(sum_j o[j]*Wp[e][j][d] + bp[e][d])
    {
        const float* Wpe = Wp + (size_t)e*DD*DD;
        float b0=0.f, b1=0.f, b2=0.f, b3=0.f;
        for (int j = 0; j < DD; j += 4) {
            b0 += sO[j  ] * Wpe[(j  )*DD + tid];
            b1 += sO[j+1] * Wpe[(j+1)*DD + tid];
            b2 += sO[j+2] * Wpe[(j+2)*DD + tid];
            b3 += sO[j+3] * Wpe[(j+3)*DD + tid];
        }
        float gsum = b0 + b1 + b2 + b3 + bp[e*DD + tid];
        d_gates[eb*DD + tid] = 1.f / (1.f + expf(-gsum));
    }
}

// ============ K4: combine + loss (block 0) + counter reset ============
__global__ void __launch_bounds__(256) k_combine(
    const float* __restrict__ x, float* __restrict__ out, int out_size)
{
    __shared__ float red[128];
    int tid = threadIdx.x;
    int token = blockIdx.x*4 + (tid >> 6);
    int q = tid & 63;
    int b = token >> 11;
    int i1 = d_idx1[token], i2 = d_idx2[token];
    float w1 = d_g1[token], w2 = d_g2[token];
    float4 xv = ((const float4*)x)[(size_t)token*64 + q];
    float4 ga = ((const float4*)(d_gates + (i1*BB + b)*DD))[q];
    float4 gb = ((const float4*)(d_gates + (i2*BB + b)*DD))[q];
    float4 o;
    o.x = xv.x * (w1*ga.x + w2*gb.x);
    o.y = xv.y * (w1*ga.y + w2*gb.y);
    o.z = xv.z * (w1*ga.z + w2*gb.z);
    o.w = xv.w * (w1*ga.w + w2*gb.w);
    ((float4*)out)[(size_t)token*64 + q] = o;

    if (blockIdx.x == 0) {
        if (tid < 128) {
            red[tid] = d_probsum[tid] * (float)d_count1[tid];
            // reset counters for the next (deterministic) run
            d_probsum[tid] = 0.f;
            d_count1[tid] = 0;
        }
        __syncthreads();
        if (tid < 64) red[tid] += red[tid + 64];
        __syncthreads();
        if (tid < 32) {
            float v = red[tid] + red[tid + 32];
#pragma unroll
            for (int off = 16; off > 0; off >>= 1)
                v += __shfl_xor_sync(0xffffffffu, v, off);
            if (tid == 0 && out_size > NTOK*DD) {
                float coef = (float)(EE*EE) * 0.01f / ((float)NN * (float)NN * (float)(BB*EE));
                out[NTOK*DD] = v * coef;
            }
        }
    }
}

// ------------------------- launch -------------------------
extern "C" void kernel_launch(void* const* d_in, const int* in_sizes, int n_in,
                              void* d_out, int out_size) {
    const float* x     = (const float*)d_in[0];
    const float* audio = (const float*)d_in[1];
    const float* wg    = (const float*)d_in[2];
    const float* Wq    = (const float*)d_in[3];
    const float* Wkv   = (const float*)d_in[4];
    const float* Wp    = (const float*)d_in[5];
    const float* bp    = (const float*)d_in[6];
    float* out = (float*)d_out;

    k_gate_qU<<<NTOK/8, 256>>>(x, audio, wg, Wq, Wkv);
    k_poslogy<<<EB*4, 256>>>(x);
    k_finish<<<EB, 256>>>(Wkv, Wp, bp);
    k_combine<<<NTOK/4, 256>>>(x, out, out_size);
}

// round 7
// speedup vs baseline: 1.1706x; 1.1706x over previous
#include <cuda_runtime.h>
#include <math.h>

#define BB   8
#define NN   2048
#define DD   256
#define EE   16
#define HH   8
#define CAPC 256
#define NTOK (BB*NN)
#define EB   128

// ------------------------- device scratch (no allocs; zero-initialized) ----------
__device__ int   d_idx1[NTOK];
__device__ int   d_idx2[NTOK];
__device__ float d_g1[NTOK];
__device__ float d_g2[NTOK];
__device__ float d_probsum[BB*EE];      // zeroed at load; re-zeroed each run in k_combine
__device__ int   d_count1[BB*EE];
__device__ int   d_slot_tok[EB*CAPC];
__device__ float d_logits[EB*HH*CAPC];
__device__ float d_py[EB*4*HH*DD];      // per-quarter partial y
__device__ float d_gates[EB*DD];

// ============ K1: gating, warp per token; wg transposed into smem ============
__global__ void __launch_bounds__(256) k_gating(
    const float* __restrict__ x, const float* __restrict__ wg)
{
    __shared__ float swgT[EE*260];          // [e][d], pad 260 to dodge conflicts
    __shared__ float sprob[EE];
    __shared__ int   scnt[EE];

    int tid = threadIdx.x, lane = tid & 31, warp = tid >> 5;
    if (tid < EE) { sprob[tid] = 0.f; scnt[tid] = 0; }
    // transpose wg[d][e] -> swgT[e][d]
    for (int i = tid; i < DD*EE; i += 256)
        swgT[(i & 15)*260 + (i >> 4)] = wg[i];
    __syncthreads();

    int token = blockIdx.x * 8 + warp;      // 8 tokens/block, same b
    const float4* xr4 = (const float4*)(x + (size_t)token * DD);
    float4 xa = xr4[lane], xb = xr4[lane + 32];

    float p[EE];
#pragma unroll
    for (int e = 0; e < EE; e++) {
        const float4* w4 = (const float4*)(swgT + e*260);
        float4 wa = w4[lane], wb = w4[lane + 32];
        p[e] = xa.x*wa.x + xa.y*wa.y + xa.z*wa.z + xa.w*wa.w
             + xb.x*wb.x + xb.y*wb.y + xb.z*wb.z + xb.w*wb.w;
    }
#pragma unroll
    for (int e = 0; e < EE; e++) {
#pragma unroll
        for (int off = 16; off > 0; off >>= 1)
            p[e] += __shfl_xor_sync(0xffffffffu, p[e], off);
    }
    // softmax over 16
    float mx = p[0];
#pragma unroll
    for (int e = 1; e < EE; e++) mx = fmaxf(mx, p[e]);
    float s = 0.f;
#pragma unroll
    for (int e = 0; e < EE; e++) { p[e] = expf(p[e] - mx); s += p[e]; }
    float inv = 1.f / s;
#pragma unroll
    for (int e = 0; e < EE; e++) p[e] *= inv;
    // top-1 / top-2 (first-max tie break)
    int i1 = 0; float g1v = p[0];
#pragma unroll
    for (int e = 1; e < EE; e++) if (p[e] > g1v) { g1v = p[e]; i1 = e; }
    int i2 = (i1 == 0) ? 1 : 0; float g2v = p[i2];
#pragma unroll
    for (int e = 0; e < EE; e++)
        if (e != i1 && p[e] > g2v) { g2v = p[e]; i2 = e; }
    float denom = g1v + g2v + 1e-9f;

    if (lane == 0) {
        d_idx1[token] = i1; d_idx2[token] = i2;
        d_g1[token] = g1v / denom; d_g2[token] = g2v / denom;
        atomicAdd(&scnt[i1], 1);
    }
    if (lane < EE) atomicAdd(&sprob[lane], p[lane]);
    __syncthreads();
    if (tid < EE) {
        int b = (blockIdx.x * 8) >> 11;
        atomicAdd(&d_probsum[b*EE + tid], sprob[tid]);
        atomicAdd(&d_count1[b*EE + tid], scnt[tid]);
    }
}

// ==== K2: qU (redundant) + ballot capacity scan (redundant) + logits for 64 slots ====
__global__ void __launch_bounds__(256) k_logits(
    const float* __restrict__ x, const float* __restrict__ audio,
    const float* __restrict__ Wq, const float* __restrict__ Wkv)
{
    __shared__ float sa[DD];
    __shared__ float sq[DD];
    __shared__ float sU[HH][DD];
    __shared__ int   s_slots[CAPC];
    __shared__ int   swc1[8], swc2[8];
    __shared__ int   sbase1[8], sbase2[8];

    int ebq = blockIdx.x;
    int eb = ebq >> 2, qtr = ebq & 3;
    int e = eb >> 3, b = eb & 7;
    int tid = threadIdx.x, lane = tid & 31, warp = tid >> 5;

    if (tid < CAPC) s_slots[tid] = -1;
    if (tid < DD) sa[tid] = audio[b*DD + tid];
    __syncthreads();

    // ---- q[j] = sum_d audio[d]*Wq[e][d][j] ----
    const float* Wqe = Wq + (size_t)e*DD*DD;
    {
        float a0=0.f, a1=0.f, a2=0.f, a3=0.f;
        for (int d = 0; d < DD; d += 4) {
            a0 += sa[d  ] * Wqe[(d  )*DD + tid];
            a1 += sa[d+1] * Wqe[(d+1)*DD + tid];
            a2 += sa[d+2] * Wqe[(d+2)*DD + tid];
            a3 += sa[d+3] * Wqe[(d+3)*DD + tid];
        }
        sq[tid] = a0 + a1 + a2 + a3;
    }
    __syncthreads();

    // ---- U[h][d]: warp = head, 4-d unroll with shuffle reductions ----
    const float* Wkve = Wkv + (size_t)e*DD*2*DD;
    {
        int h = warp;
        float qv = sq[h*32 + lane];
        for (int d = 0; d < DD; d += 4) {
            float v0 = Wkve[(size_t)(d  )*512 + h*32 + lane] * qv;
            float v1 = Wkve[(size_t)(d+1)*512 + h*32 + lane] * qv;
            float v2 = Wkve[(size_t)(d+2)*512 + h*32 + lane] * qv;
            float v3 = Wkve[(size_t)(d+3)*512 + h*32 + lane] * qv;
#pragma unroll
            for (int off = 16; off > 0; off >>= 1) {
                v0 += __shfl_xor_sync(0xffffffffu, v0, off);
                v1 += __shfl_xor_sync(0xffffffffu, v1, off);
                v2 += __shfl_xor_sync(0xffffffffu, v2, off);
                v3 += __shfl_xor_sync(0xffffffffu, v3, off);
            }
            if (lane == 0) { sU[h][d] = v0; sU[h][d+1] = v1; sU[h][d+2] = v2; sU[h][d+3] = v3; }
        }
    }

    // ---- ballot-based capacity scan (full, redundant per quarter) ----
    unsigned m1[8], m2[8];
    {
        int wc1 = 0, wc2 = 0;
#pragma unroll
        for (int r = 0; r < 8; r++) {
            int t = warp*256 + r*32 + lane;
            int v1 = d_idx1[b*NN + t];
            int v2 = d_idx2[b*NN + t];
            m1[r] = __ballot_sync(0xffffffffu, v1 == e);
            m2[r] = __ballot_sync(0xffffffffu, v2 == e);
            wc1 += __popc(m1[r]); wc2 += __popc(m2[r]);
        }
        if (lane == 0) { swc1[warp] = wc1; swc2[warp] = wc2; }
    }
    __syncthreads();
    if (tid == 0) {
        int run = 0;
        for (int w = 0; w < 8; w++) { sbase1[w] = run; run += swc1[w]; }
        int base2 = (run < CAPC) ? run : CAPC;     // m1_count capped
        for (int w = 0; w < 8; w++) { sbase2[w] = base2; base2 += swc2[w]; }
    }
    __syncthreads();
    {
        unsigned ltmask = (1u << lane) - 1u;
        int run = sbase1[warp];
#pragma unroll
        for (int r = 0; r < 8; r++) {
            unsigned m = m1[r];
            if (m & (1u << lane)) {
                int slot = run + __popc(m & ltmask);
                int t = warp*256 + r*32 + lane;
                if (slot < CAPC) s_slots[slot] = t;
                else if (qtr == 0) d_g1[b*NN + t] = 0.f;
            }
            run += __popc(m);
        }
        run = sbase2[warp];
#pragma unroll
        for (int r = 0; r < 8; r++) {
            unsigned m = m2[r];
            if (m & (1u << lane)) {
                int slot = run + __popc(m & ltmask);
                int t = warp*256 + r*32 + lane;
                if (slot < CAPC) s_slots[slot] = t;
                else if (qtr == 0) d_g2[b*NN + t] = 0.f;
            }
            run += __popc(m);
        }
    }
    __syncthreads();
    // publish our quarter of the slot table
    if (tid < 64) d_slot_tok[eb*CAPC + qtr*64 + tid] = s_slots[qtr*64 + tid];

    // ---- logits for this quarter's 64 slots (warp handles 8) ----
    const float scale = 0.17677669529663687f;    // 32^-0.5
#pragma unroll
    for (int ci = 0; ci < 8; ci++) {
        int slot = qtr*64 + warp*8 + ci;
        int tok = s_slots[slot];
        float part[HH];
        if (tok >= 0) {
            const float4* xr4 = (const float4*)(x + ((size_t)b*NN + tok)*DD);
            float4 xa = xr4[lane], xb = xr4[lane + 32];
#pragma unroll
            for (int h = 0; h < HH; h++) {
                const float4* u4 = (const float4*)(&sU[h][0]);
                float4 ua = u4[lane], ub = u4[lane + 32];
                part[h] = xa.x*ua.x + xa.y*ua.y + xa.z*ua.z + xa.w*ua.w
                        + xb.x*ub.x + xb.y*ub.y + xb.z*ub.z + xb.w*ub.w;
            }
        } else {
#pragma unroll
            for (int h = 0; h < HH; h++) part[h] = 0.f;
        }
#pragma unroll
        for (int h = 0; h < HH; h++) {
            float v = part[h];
#pragma unroll
            for (int off = 16; off > 0; off >>= 1)
                v += __shfl_xor_sync(0xffffffffu, v, off);
            if (lane == 0)
                d_logits[(eb*HH + h)*CAPC + slot] = (tok >= 0) ? v * scale : 0.f;
        }
    }
}

// ======== K3: softmax (redundant per quarter) + partial y for 64 slots ========
__global__ void __launch_bounds__(256) k_y(const float* __restrict__ x) {
    __shared__ float satt[HH][CAPC];
    __shared__ int   stok[64];

    int ebq = blockIdx.x;
    int eb = ebq >> 2, qtr = ebq & 3;
    int b = eb & 7;
    int tid = threadIdx.x, lane = tid & 31, warp = tid >> 5;

    if (tid < 64) stok[tid] = d_slot_tok[eb*CAPC + qtr*64 + tid];
    // softmax: warp h over its 256-slot row
    {
        int h = warp;
        const float* row = d_logits + (eb*HH + h)*CAPC;
        float vals[8];
        float mx = -1e30f;
#pragma unroll
        for (int k = 0; k < 8; k++) { vals[k] = row[lane + 32*k]; mx = fmaxf(mx, vals[k]); }
#pragma unroll
        for (int off = 16; off > 0; off >>= 1)
            mx = fmaxf(mx, __shfl_xor_sync(0xffffffffu, mx, off));
        float s = 0.f;
#pragma unroll
        for (int k = 0; k < 8; k++) { vals[k] = expf(vals[k] - mx); s += vals[k]; }
#pragma unroll
        for (int off = 16; off > 0; off >>= 1)
            s += __shfl_xor_sync(0xffffffffu, s, off);
        float inv = 1.f / s;
#pragma unroll
        for (int k = 0; k < 8; k++) satt[h][lane + 32*k] = vals[k] * inv;
    }
    __syncthreads();

    // partial y over own 64 slots (thread = d)
    float yv[HH];
#pragma unroll
    for (int h = 0; h < HH; h++) yv[h] = 0.f;
#pragma unroll 2
    for (int ci = 0; ci < 64; ci++) {
        int tok = stok[ci];
        if (tok >= 0) {
            float xv = x[((size_t)b*NN + tok)*DD + tid];
            int c = qtr*64 + ci;
#pragma unroll
            for (int h = 0; h < HH; h++) yv[h] += satt[h][c] * xv;
        }
    }
#pragma unroll
    for (int h = 0; h < HH; h++)
        d_py[((size_t)ebq*HH + h)*DD + tid] = yv[h];
}

// ============ K4: merge partials + o-projection + sigmoid gate ============
__global__ void __launch_bounds__(256) k_og(
    const float* __restrict__ Wkv, const float* __restrict__ Wp,
    const float* __restrict__ bp)
{
    __shared__ float sY[HH][DD];
    __shared__ float sO[DD];

    int eb = blockIdx.x;
    int e = eb >> 3;
    int tid = threadIdx.x;

#pragma unroll
    for (int h = 0; h < HH; h++) {
        sY[h][tid] = d_py[((size_t)(eb*4+0)*HH + h)*DD + tid]
                   + d_py[((size_t)(eb*4+1)*HH + h)*DD + tid]
                   + d_py[((size_t)(eb*4+2)*HH + h)*DD + tid]
                   + d_py[((size_t)(eb*4+3)*HH + h)*DD + tid];
    }
    __syncthreads();

    // o[j] = sum_d y[h(j)][d] * Wkv_v[e][d][256+j]
    const float* Wkve = Wkv + (size_t)e*DD*2*DD;
    {
        int h = tid >> 5;
        float a0=0.f, a1=0.f, a2=0.f, a3=0.f;
        for (int d = 0; d < DD; d += 4) {
            a0 += sY[h][d  ] * Wkve[(size_t)(d  )*512 + 256 + tid];
            a1 += sY[h][d+1] * Wkve[(size_t)(d+1)*512 + 256 + tid];
            a2 += sY[h][d+2] * Wkve[(size_t)(d+2)*512 + 256 + tid];
            a3 += sY[h][d+3] * Wkve[(size_t)(d+3)*512 + 256 + tid];
        }
        sO[tid] = a0 + a1 + a2 + a3;
    }
    __syncthreads();

    // gate[d] = sigmoid(sum_j o[j]*Wp[e][j][d] + bp[e][d])
    {
        const float* Wpe = Wp + (size_t)e*DD*DD;
        float b0=0.f, b1=0.f, b2=0.f, b3=0.f;
        for (int j = 0; j < DD; j += 4) {
            b0 += sO[j  ] * Wpe[(j  )*DD + tid];
            b1 += sO[j+1] * Wpe[(j+1)*DD + tid];
            b2 += sO[j+2] * Wpe[(j+2)*DD + tid];
            b3 += sO[j+3] * Wpe[(j+3)*DD + tid];
        }
        float gsum = b0 + b1 + b2 + b3 + bp[e*DD + tid];
        d_gates[eb*DD + tid] = 1.f / (1.f + expf(-gsum));
    }
}

// ============ K5: combine + loss (block 0) + counter reset ============
__global__ void __launch_bounds__(256) k_combine(
    const float* __restrict__ x, float* __restrict__ out, int out_size)
{
    __shared__ float red[128];
    int tid = threadIdx.x;
    int token = blockIdx.x*4 + (tid >> 6);
    int q = tid & 63;
    int b = token >> 11;
    int i1 = d_idx1[token], i2 = d_idx2[token];
    float w1 = d_g1[token], w2 = d_g2[token];
    float4 xv = ((const float4*)x)[(size_t)token*64 + q];
    float4 ga = ((const float4*)(d_gates + (i1*BB + b)*DD))[q];
    float4 gb = ((const float4*)(d_gates + (i2*BB + b)*DD))[q];
    float4 o;
    o.x = xv.x * (w1*ga.x + w2*gb.x);
    o.y = xv.y * (w1*ga.y + w2*gb.y);
    o.z = xv.z * (w1*ga.z + w2*gb.z);
    o.w = xv.w * (w1*ga.w + w2*gb.w);
    ((float4*)out)[(size_t)token*64 + q] = o;

    if (blockIdx.x == 0) {
        if (tid < 128) {
            red[tid] = d_probsum[tid] * (float)d_count1[tid];
            d_probsum[tid] = 0.f;          // reset for next (deterministic) run
            d_count1[tid] = 0;
        }
        __syncthreads();
        if (tid < 64) red[tid] += red[tid + 64];
        __syncthreads();
        if (tid < 32) {
            float v = red[tid] + red[tid + 32];
#pragma unroll
            for (int off = 16; off > 0; off >>= 1)
                v += __shfl_xor_sync(0xffffffffu, v, off);
            if (tid == 0 && out_size > NTOK*DD) {
                float coef = (float)(EE*EE) * 0.01f / ((float)NN * (float)NN * (float)(BB*EE));
                out[NTOK*DD] = v * coef;
            }
        }
    }
}

// ------------------------- launch -------------------------
extern "C" void kernel_launch(void* const* d_in, const int* in_sizes, int n_in,
                              void* d_out, int out_size) {
    const float* x     = (const float*)d_in[0];
    const float* audio = (const float*)d_in[1];
    const float* wg    = (const float*)d_in[2];
    const float* Wq    = (const float*)d_in[3];
    const float* Wkv   = (const float*)d_in[4];
    const float* Wp    = (const float*)d_in[5];
    const float* bp    = (const float*)d_in[6];
    float* out = (float*)d_out;

    k_gating<<<NTOK/8, 256>>>(x, wg);
    k_logits<<<EB*4, 256>>>(x, audio, Wq, Wkv);
    k_y<<<EB*4, 256>>>(x);
    k_og<<<EB, 256>>>(Wkv, Wp, bp);
    k_combine<<<NTOK/4, 256>>>(x, out, out_size);
}

// round 8
// speedup vs baseline: 1.5026x; 1.2836x over previous
#include <cuda_runtime.h>
#include <math.h>

#define BB   8
#define NN   2048
#define DD   256
#define EE   16
#define HH   8
#define CAPC 256
#define NTOK (BB*NN)
#define EB   128

// ------------------------- device scratch (no allocs; zero-initialized) ----------
__device__ int   d_idx1[NTOK];
__device__ int   d_idx2[NTOK];
__device__ float d_g1[NTOK];
__device__ float d_g2[NTOK];
__device__ float d_probsum[BB*EE];      // zeroed at load; re-zeroed each run in k_combine
__device__ int   d_count1[BB*EE];
__device__ int   d_slot_tok[EB*CAPC];
__device__ float d_U[EB*HH*DD];         // per-(e,b) q projected through Wkv_k
__device__ float d_logits[EB*HH*CAPC];
__device__ float d_py[EB*4*HH*DD];      // per-quarter partial y
__device__ float d_gates[EB*DD];

// ============ K1: gating, warp per token; wg transposed into smem ============
__global__ void __launch_bounds__(256) k_gating(
    const float* __restrict__ x, const float* __restrict__ wg)
{
    __shared__ float swgT[EE*260];          // [e][d], pad 260 to dodge conflicts
    __shared__ float sprob[EE];
    __shared__ int   scnt[EE];

    int tid = threadIdx.x, lane = tid & 31, warp = tid >> 5;
    if (tid < EE) { sprob[tid] = 0.f; scnt[tid] = 0; }
    for (int i = tid; i < DD*EE; i += 256)
        swgT[(i & 15)*260 + (i >> 4)] = wg[i];
    __syncthreads();

    int token = blockIdx.x * 8 + warp;      // 8 tokens/block, same b
    const float4* xr4 = (const float4*)(x + (size_t)token * DD);
    float4 xa = xr4[lane], xb = xr4[lane + 32];

    float p[EE];
#pragma unroll
    for (int e = 0; e < EE; e++) {
        const float4* w4 = (const float4*)(swgT + e*260);
        float4 wa = w4[lane], wb = w4[lane + 32];
        p[e] = xa.x*wa.x + xa.y*wa.y + xa.z*wa.z + xa.w*wa.w
             + xb.x*wb.x + xb.y*wb.y + xb.z*wb.z + xb.w*wb.w;
    }
#pragma unroll
    for (int e = 0; e < EE; e++) {
#pragma unroll
        for (int off = 16; off > 0; off >>= 1)
            p[e] += __shfl_xor_sync(0xffffffffu, p[e], off);
    }
    float mx = p[0];
#pragma unroll
    for (int e = 1; e < EE; e++) mx = fmaxf(mx, p[e]);
    float s = 0.f;
#pragma unroll
    for (int e = 0; e < EE; e++) { p[e] = expf(p[e] - mx); s += p[e]; }
    float inv = 1.f / s;
#pragma unroll
    for (int e = 0; e < EE; e++) p[e] *= inv;
    int i1 = 0; float g1v = p[0];
#pragma unroll
    for (int e = 1; e < EE; e++) if (p[e] > g1v) { g1v = p[e]; i1 = e; }
    int i2 = (i1 == 0) ? 1 : 0; float g2v = p[i2];
#pragma unroll
    for (int e = 0; e < EE; e++)
        if (e != i1 && p[e] > g2v) { g2v = p[e]; i2 = e; }
    float denom = g1v + g2v + 1e-9f;

    if (lane == 0) {
        d_idx1[token] = i1; d_idx2[token] = i2;
        d_g1[token] = g1v / denom; d_g2[token] = g2v / denom;
        atomicAdd(&scnt[i1], 1);
    }
    if (lane < EE) atomicAdd(&sprob[lane], p[lane]);
    __syncthreads();
    if (tid < EE) {
        int b = (blockIdx.x * 8) >> 11;
        atomicAdd(&d_probsum[b*EE + tid], sprob[tid]);
        atomicAdd(&d_count1[b*EE + tid], scnt[tid]);
    }
}

// ============ K2: qU, block per (e,b), 1024 threads, 4-way split ============
__global__ void __launch_bounds__(1024, 1) k_qU(
    const float* __restrict__ audio, const float* __restrict__ Wq,
    const float* __restrict__ Wkv)
{
    __shared__ float sa[DD];
    __shared__ float sq[DD];
    __shared__ float sRed[4][DD];

    int e = blockIdx.x >> 3;
    int b = blockIdx.x & 7;
    int tid = threadIdx.x, lane = tid & 31, warp = tid >> 5;
    int g = tid >> 8, wtid = tid & 255;

    if (tid < DD) sa[tid] = audio[b*DD + tid];
    __syncthreads();

    const float* Wqe = Wq + (size_t)e*DD*DD;
    {
        float acc = 0.f;
        int d0 = g*64;
#pragma unroll 4
        for (int d = d0; d < d0 + 64; d++) acc += sa[d] * Wqe[d*DD + wtid];
        sRed[g][wtid] = acc;
    }
    __syncthreads();
    if (tid < DD)
        sq[tid] = sRed[0][tid] + sRed[1][tid] + sRed[2][tid] + sRed[3][tid];
    __syncthreads();

    const float* Wkve = Wkv + (size_t)e*DD*2*DD;
    {
        int h = warp & 7;
        int dbase = (warp >> 3) * 64;
        float qv = sq[h*32 + lane];
        float* Urow = d_U + ((size_t)blockIdx.x*HH + h)*DD;
#pragma unroll 4
        for (int d = dbase; d < dbase + 64; d++) {
            float v = Wkve[(size_t)d*512 + h*32 + lane] * qv;
#pragma unroll
            for (int off = 16; off > 0; off >>= 1)
                v += __shfl_xor_sync(0xffffffffu, v, off);
            if (lane == 0) Urow[d] = v;
        }
    }
}

// ==== K3: ballot capacity scan (redundant per quarter) + logits for 64 slots ====
__global__ void __launch_bounds__(256) k_poslog(const float* __restrict__ x) {
    __shared__ float sU[HH][DD];
    __shared__ int   s_slots[CAPC];
    __shared__ int   swc1[8], swc2[8];
    __shared__ int   sbase1[8], sbase2[8];

    int ebq = blockIdx.x;
    int eb = ebq >> 2, qtr = ebq & 3;
    int e = eb >> 3, b = eb & 7;
    int tid = threadIdx.x, lane = tid & 31, warp = tid >> 5;

    if (tid < CAPC) s_slots[tid] = -1;
#pragma unroll
    for (int k = 0; k < 8; k++)
        ((float*)sU)[k*256 + tid] = d_U[(size_t)eb*2048 + k*256 + tid];

    // ---- ballot-based capacity scan ----
    unsigned m1[8], m2[8];
    {
        int wc1 = 0, wc2 = 0;
#pragma unroll
        for (int r = 0; r < 8; r++) {
            int t = warp*256 + r*32 + lane;
            int v1 = d_idx1[b*NN + t];
            int v2 = d_idx2[b*NN + t];
            m1[r] = __ballot_sync(0xffffffffu, v1 == e);
            m2[r] = __ballot_sync(0xffffffffu, v2 == e);
            wc1 += __popc(m1[r]); wc2 += __popc(m2[r]);
        }
        if (lane == 0) { swc1[warp] = wc1; swc2[warp] = wc2; }
    }
    __syncthreads();
    if (tid == 0) {
        int run = 0;
        for (int w = 0; w < 8; w++) { sbase1[w] = run; run += swc1[w]; }
        int base2 = (run < CAPC) ? run : CAPC;     // m1_count capped
        for (int w = 0; w < 8; w++) { sbase2[w] = base2; base2 += swc2[w]; }
    }
    __syncthreads();
    {
        unsigned ltmask = (1u << lane) - 1u;
        int run = sbase1[warp];
#pragma unroll
        for (int r = 0; r < 8; r++) {
            unsigned m = m1[r];
            if (m & (1u << lane)) {
                int slot = run + __popc(m & ltmask);
                int t = warp*256 + r*32 + lane;
                if (slot < CAPC) s_slots[slot] = t;
                else if (qtr == 0) d_g1[b*NN + t] = 0.f;
            }
            run += __popc(m);
        }
        run = sbase2[warp];
#pragma unroll
        for (int r = 0; r < 8; r++) {
            unsigned m = m2[r];
            if (m & (1u << lane)) {
                int slot = run + __popc(m & ltmask);
                int t = warp*256 + r*32 + lane;
                if (slot < CAPC) s_slots[slot] = t;
                else if (qtr == 0) d_g2[b*NN + t] = 0.f;
            }
            run += __popc(m);
        }
    }
    __syncthreads();
    if (tid < 64) d_slot_tok[eb*CAPC + qtr*64 + tid] = s_slots[qtr*64 + tid];

    // ---- logits for this quarter's 64 slots (warp handles 8) ----
    const float scale = 0.17677669529663687f;    // 32^-0.5
#pragma unroll
    for (int ci = 0; ci < 8; ci++) {
        int slot = qtr*64 + warp*8 + ci;
        int tok = s_slots[slot];
        float part[HH];
        if (tok >= 0) {
            const float4* xr4 = (const float4*)(x + ((size_t)b*NN + tok)*DD);
            float4 xa = xr4[lane], xb = xr4[lane + 32];
#pragma unroll
            for (int h = 0; h < HH; h++) {
                const float4* u4 = (const float4*)(&sU[h][0]);
                float4 ua = u4[lane], ub = u4[lane + 32];
                part[h] = xa.x*ua.x + xa.y*ua.y + xa.z*ua.z + xa.w*ua.w
                        + xb.x*ub.x + xb.y*ub.y + xb.z*ub.z + xb.w*ub.w;
            }
        } else {
#pragma unroll
            for (int h = 0; h < HH; h++) part[h] = 0.f;
        }
#pragma unroll
        for (int h = 0; h < HH; h++) {
            float v = part[h];
#pragma unroll
            for (int off = 16; off > 0; off >>= 1)
                v += __shfl_xor_sync(0xffffffffu, v, off);
            if (lane == 0)
                d_logits[(eb*HH + h)*CAPC + slot] = (tok >= 0) ? v * scale : 0.f;
        }
    }
}

// ======== K4: softmax (redundant per quarter) + partial y for 64 slots ========
__global__ void __launch_bounds__(256) k_y(const float* __restrict__ x) {
    __shared__ float satt[HH][CAPC];
    __shared__ int   stok[64];

    int ebq = blockIdx.x;
    int eb = ebq >> 2, qtr = ebq & 3;
    int b = eb & 7;
    int tid = threadIdx.x, lane = tid & 31, warp = tid >> 5;

    if (tid < 64) stok[tid] = d_slot_tok[eb*CAPC + qtr*64 + tid];
    {
        int h = warp;
        const float* row = d_logits + (eb*HH + h)*CAPC;
        float vals[8];
        float mx = -1e30f;
#pragma unroll
        for (int k = 0; k < 8; k++) { vals[k] = row[lane + 32*k]; mx = fmaxf(mx, vals[k]); }
#pragma unroll
        for (int off = 16; off > 0; off >>= 1)
            mx = fmaxf(mx, __shfl_xor_sync(0xffffffffu, mx, off));
        float s = 0.f;
#pragma unroll
        for (int k = 0; k < 8; k++) { vals[k] = expf(vals[k] - mx); s += vals[k]; }
#pragma unroll
        for (int off = 16; off > 0; off >>= 1)
            s += __shfl_xor_sync(0xffffffffu, s, off);
        float inv = 1.f / s;
#pragma unroll
        for (int k = 0; k < 8; k++) satt[h][lane + 32*k] = vals[k] * inv;
    }
    __syncthreads();

    float yv[HH];
#pragma unroll
    for (int h = 0; h < HH; h++) yv[h] = 0.f;
#pragma unroll 2
    for (int ci = 0; ci < 64; ci++) {
        int tok = stok[ci];
        if (tok >= 0) {
            float xv = x[((size_t)b*NN + tok)*DD + tid];
            int c = qtr*64 + ci;
#pragma unroll
            for (int h = 0; h < HH; h++) yv[h] += satt[h][c] * xv;
        }
    }
#pragma unroll
    for (int h = 0; h < HH; h++)
        d_py[((size_t)ebq*HH + h)*DD + tid] = yv[h];
}

// ==== K5: merge partials + o-projection + sigmoid gate; 1024 threads, 4-way split ====
__global__ void __launch_bounds__(1024, 1) k_og(
    const float* __restrict__ Wkv, const float* __restrict__ Wp,
    const float* __restrict__ bp)
{
    __shared__ float sY[HH][DD];
    __shared__ float sO[DD];
    __shared__ float sRed[4][DD];

    int eb = blockIdx.x;
    int e = eb >> 3;
    int tid = threadIdx.x;
    int g = tid >> 8, wtid = tid & 255;

    for (int i = tid; i < HH*DD; i += 1024) {
        ((float*)sY)[i] = d_py[(size_t)(eb*4+0)*2048 + i]
                        + d_py[(size_t)(eb*4+1)*2048 + i]
                        + d_py[(size_t)(eb*4+2)*2048 + i]
                        + d_py[(size_t)(eb*4+3)*2048 + i];
    }
    __syncthreads();

    // o[j] = sum_d y[h(j)][d] * Wkv_v[e][d][256+j]; 4-way split over d
    const float* Wkve = Wkv + (size_t)e*DD*2*DD;
    {
        int h = wtid >> 5;
        float acc = 0.f;
        int d0 = g*64;
#pragma unroll 4
        for (int d = d0; d < d0 + 64; d++)
            acc += sY[h][d] * Wkve[(size_t)d*512 + 256 + wtid];
        sRed[g][wtid] = acc;
    }
    __syncthreads();
    if (tid < DD)
        sO[tid] = sRed[0][tid] + sRed[1][tid] + sRed[2][tid] + sRed[3][tid];
    __syncthreads();

    // gate[d] = sigmoid(sum_j o[j]*Wp[e][j][d] + bp[e][d]); 4-way split over j
    {
        const float* Wpe = Wp + (size_t)e*DD*DD;
        float acc = 0.f;
        int j0 = g*64;
#pragma unroll 4
        for (int j = j0; j < j0 + 64; j++) acc += sO[j] * Wpe[j*DD + wtid];
        sRed[g][wtid] = acc;
    }
    __syncthreads();
    if (tid < DD) {
        float gsum = sRed[0][tid] + sRed[1][tid] + sRed[2][tid] + sRed[3][tid]
                   + bp[e*DD + tid];
        d_gates[eb*DD + tid] = 1.f / (1.f + expf(-gsum));
    }
}

// ============ K6: combine + loss (block 0) + counter reset ============
__global__ void __launch_bounds__(256) k_combine(
    const float* __restrict__ x, float* __restrict__ out, int out_size)
{
    __shared__ float red[128];
    int tid = threadIdx.x;
    int token = blockIdx.x*4 + (tid >> 6);
    int q = tid & 63;
    int b = token >> 11;
    int i1 = d_idx1[token], i2 = d_idx2[token];
    float w1 = d_g1[token], w2 = d_g2[token];
    float4 xv = ((const float4*)x)[(size_t)token*64 + q];
    float4 ga = ((const float4*)(d_gates + (i1*BB + b)*DD))[q];
    float4 gb = ((const float4*)(d_gates + (i2*BB + b)*DD))[q];
    float4 o;
    o.x = xv.x * (w1*ga.x + w2*gb.x);
    o.y = xv.y * (w1*ga.y + w2*gb.y);
    o.z = xv.z * (w1*ga.z + w2*gb.z);
    o.w = xv.w * (w1*ga.w + w2*gb.w);
    ((float4*)out)[(size_t)token*64 + q] = o;

    if (blockIdx.x == 0) {
        if (tid < 128) {
            red[tid] = d_probsum[tid] * (float)d_count1[tid];
            d_probsum[tid] = 0.f;          // reset for next (deterministic) run
            d_count1[tid] = 0;
        }
        __syncthreads();
        if (tid < 64) red[tid] += red[tid + 64];
        __syncthreads();
        if (tid < 32) {
            float v = red[tid] + red[tid + 32];
#pragma unroll
            for (int off = 16; off > 0; off >>= 1)
                v += __shfl_xor_sync(0xffffffffu, v, off);
            if (tid == 0 && out_size > NTOK*DD) {
                float coef = (float)(EE*EE) * 0.01f / ((float)NN * (float)NN * (float)(BB*EE));
                out[NTOK*DD] = v * coef;
            }
        }
    }
}

// ------------------------- launch -------------------------
extern "C" void kernel_launch(void* const* d_in, const int* in_sizes, int n_in,
                              void* d_out, int out_size) {
    const float* x     = (const float*)d_in[0];
    const float* audio = (const float*)d_in[1];
    const float* wg    = (const float*)d_in[2];
    const float* Wq    = (const float*)d_in[3];
    const float* Wkv   = (const float*)d_in[4];
    const float* Wp    = (const float*)d_in[5];
    const float* bp    = (const float*)d_in[6];
    float* out = (float*)d_out;

    k_gating<<<NTOK/8, 256>>>(x, wg);
    k_qU<<<EB, 1024>>>(audio, Wq, Wkv);
    k_poslog<<<EB*4, 256>>>(x);
    k_y<<<EB*4, 256>>>(x);
    k_og<<<EB, 1024>>>(Wkv, Wp, bp);
    k_combine<<<NTOK/4, 256>>>(x, out, out_size);
}

// round 9
// speedup vs baseline: 1.5366x; 1.0226x over previous
#include <cuda_runtime.h>
#include <math.h>

#define BB   8
#define NN   2048
#define DD   256
#define EE   16
#define HH   8
#define CAPC 256
#define NTOK (BB*NN)
#define EB   128
#define NG   8          // slot-groups per (e,b): 32 slots each

// ------------------------- device scratch (no allocs; zero-initialized) ----------
__device__ int   d_idx1[NTOK];
__device__ int   d_idx2[NTOK];
__device__ float d_g1[NTOK];
__device__ float d_g2[NTOK];
__device__ float d_probsum[BB*EE];      // zeroed at load; re-zeroed each run in k_combine
__device__ int   d_count1[BB*EE];
__device__ int   d_slot_tok[EB*CAPC];
__device__ float d_U[EB*HH*DD];         // per-(e,b) q projected through Wkv_k
__device__ float d_logits[EB*HH*CAPC];
__device__ float d_py[EB*NG*HH*DD];     // per-group partial y
__device__ float d_gates[EB*DD];

// ============ K1: gating, warp per token; wg transposed into smem ============
__global__ void __launch_bounds__(256) k_gating(
    const float* __restrict__ x, const float* __restrict__ wg)
{
    __shared__ float swgT[EE*260];
    __shared__ float sprob[EE];
    __shared__ int   scnt[EE];

    int tid = threadIdx.x, lane = tid & 31, warp = tid >> 5;
    if (tid < EE) { sprob[tid] = 0.f; scnt[tid] = 0; }
    for (int i = tid; i < DD*EE; i += 256)
        swgT[(i & 15)*260 + (i >> 4)] = wg[i];
    __syncthreads();

    int token = blockIdx.x * 8 + warp;      // 8 tokens/block, same b
    const float4* xr4 = (const float4*)(x + (size_t)token * DD);
    float4 xa = xr4[lane], xb = xr4[lane + 32];

    float p[EE];
#pragma unroll
    for (int e = 0; e < EE; e++) {
        const float4* w4 = (const float4*)(swgT + e*260);
        float4 wa = w4[lane], wb = w4[lane + 32];
        p[e] = xa.x*wa.x + xa.y*wa.y + xa.z*wa.z + xa.w*wa.w
             + xb.x*wb.x + xb.y*wb.y + xb.z*wb.z + xb.w*wb.w;
    }
#pragma unroll
    for (int e = 0; e < EE; e++) {
#pragma unroll
        for (int off = 16; off > 0; off >>= 1)
            p[e] += __shfl_xor_sync(0xffffffffu, p[e], off);
    }
    float mx = p[0];
#pragma unroll
    for (int e = 1; e < EE; e++) mx = fmaxf(mx, p[e]);
    float s = 0.f;
#pragma unroll
    for (int e = 0; e < EE; e++) { p[e] = expf(p[e] - mx); s += p[e]; }
    float inv = 1.f / s;
#pragma unroll
    for (int e = 0; e < EE; e++) p[e] *= inv;
    int i1 = 0; float g1v = p[0];
#pragma unroll
    for (int e = 1; e < EE; e++) if (p[e] > g1v) { g1v = p[e]; i1 = e; }
    int i2 = (i1 == 0) ? 1 : 0; float g2v = p[i2];
#pragma unroll
    for (int e = 0; e < EE; e++)
        if (e != i1 && p[e] > g2v) { g2v = p[e]; i2 = e; }
    float denom = g1v + g2v + 1e-9f;

    if (lane == 0) {
        d_idx1[token] = i1; d_idx2[token] = i2;
        d_g1[token] = g1v / denom; d_g2[token] = g2v / denom;
        atomicAdd(&scnt[i1], 1);
    }
    if (lane < EE) atomicAdd(&sprob[lane], p[lane]);
    __syncthreads();
    if (tid < EE) {
        int b = (blockIdx.x * 8) >> 11;
        atomicAdd(&d_probsum[b*EE + tid], sprob[tid]);
        atomicAdd(&d_count1[b*EE + tid], scnt[tid]);
    }
}

// ============ K2: qU, block per (e,b), 1024 threads, 4-way split ============
__global__ void __launch_bounds__(1024, 1) k_qU(
    const float* __restrict__ audio, const float* __restrict__ Wq,
    const float* __restrict__ Wkv)
{
    __shared__ float sa[DD];
    __shared__ float sq[DD];
    __shared__ float sRed[4][DD];

    int e = blockIdx.x >> 3;
    int b = blockIdx.x & 7;
    int tid = threadIdx.x, lane = tid & 31, warp = tid >> 5;
    int g = tid >> 8, wtid = tid & 255;

    if (tid < DD) sa[tid] = audio[b*DD + tid];
    __syncthreads();

    const float* Wqe = Wq + (size_t)e*DD*DD;
    {
        float acc = 0.f;
        int d0 = g*64;
#pragma unroll 4
        for (int d = d0; d < d0 + 64; d++) acc += sa[d] * Wqe[d*DD + wtid];
        sRed[g][wtid] = acc;
    }
    __syncthreads();
    if (tid < DD)
        sq[tid] = sRed[0][tid] + sRed[1][tid] + sRed[2][tid] + sRed[3][tid];
    __syncthreads();

    const float* Wkve = Wkv + (size_t)e*DD*2*DD;
    {
        int h = warp & 7;
        int dbase = (warp >> 3) * 64;
        float qv = sq[h*32 + lane];
        float* Urow = d_U + ((size_t)blockIdx.x*HH + h)*DD;
#pragma unroll 4
        for (int d = dbase; d < dbase + 64; d++) {
            float v = Wkve[(size_t)d*512 + h*32 + lane] * qv;
#pragma unroll
            for (int off = 16; off > 0; off >>= 1)
                v += __shfl_xor_sync(0xffffffffu, v, off);
            if (lane == 0) Urow[d] = v;
        }
    }
}

// ==== K3: ballot capacity scan (redundant per group) + logits for 32 slots ====
__global__ void __launch_bounds__(256) k_poslog(const float* __restrict__ x) {
    __shared__ float sU[HH][DD];
    __shared__ int   s_slots[CAPC];
    __shared__ int   swc1[8], swc2[8];
    __shared__ int   sbase1[8], sbase2[8];

    int ebg = blockIdx.x;
    int eb = ebg >> 3, grp = ebg & 7;       // 8 groups of 32 slots
    int e = eb >> 3, b = eb & 7;
    int tid = threadIdx.x, lane = tid & 31, warp = tid >> 5;

    if (tid < CAPC) s_slots[tid] = -1;
#pragma unroll
    for (int k = 0; k < 8; k++)
        ((float*)sU)[k*256 + tid] = d_U[(size_t)eb*2048 + k*256 + tid];

    // ---- ballot-based capacity scan (full, redundant) ----
    unsigned m1[8], m2[8];
    {
        int wc1 = 0, wc2 = 0;
#pragma unroll
        for (int r = 0; r < 8; r++) {
            int t = warp*256 + r*32 + lane;
            int v1 = d_idx1[b*NN + t];
            int v2 = d_idx2[b*NN + t];
            m1[r] = __ballot_sync(0xffffffffu, v1 == e);
            m2[r] = __ballot_sync(0xffffffffu, v2 == e);
            wc1 += __popc(m1[r]); wc2 += __popc(m2[r]);
        }
        if (lane == 0) { swc1[warp] = wc1; swc2[warp] = wc2; }
    }
    __syncthreads();
    if (tid == 0) {
        int run = 0;
        for (int w = 0; w < 8; w++) { sbase1[w] = run; run += swc1[w]; }
        int base2 = (run < CAPC) ? run : CAPC;     // m1_count capped
        for (int w = 0; w < 8; w++) { sbase2[w] = base2; base2 += swc2[w]; }
    }
    __syncthreads();
    {
        unsigned ltmask = (1u << lane) - 1u;
        int run = sbase1[warp];
#pragma unroll
        for (int r = 0; r < 8; r++) {
            unsigned m = m1[r];
            if (m & (1u << lane)) {
                int slot = run + __popc(m & ltmask);
                int t = warp*256 + r*32 + lane;
                if (slot < CAPC) s_slots[slot] = t;
                else if (grp == 0) d_g1[b*NN + t] = 0.f;
            }
            run += __popc(m);
        }
        run = sbase2[warp];
#pragma unroll
        for (int r = 0; r < 8; r++) {
            unsigned m = m2[r];
            if (m & (1u << lane)) {
                int slot = run + __popc(m & ltmask);
                int t = warp*256 + r*32 + lane;
                if (slot < CAPC) s_slots[slot] = t;
                else if (grp == 0) d_g2[b*NN + t] = 0.f;
            }
            run += __popc(m);
        }
    }
    __syncthreads();
    if (tid < 32) d_slot_tok[eb*CAPC + grp*32 + tid] = s_slots[grp*32 + tid];

    // ---- logits for this group's 32 slots (warp handles 4) ----
    const float scale = 0.17677669529663687f;    // 32^-0.5
#pragma unroll
    for (int ci = 0; ci < 4; ci++) {
        int slot = grp*32 + warp*4 + ci;
        int tok = s_slots[slot];
        float part[HH];
        if (tok >= 0) {
            const float4* xr4 = (const float4*)(x + ((size_t)b*NN + tok)*DD);
            float4 xa = xr4[lane], xb = xr4[lane + 32];
#pragma unroll
            for (int h = 0; h < HH; h++) {
                const float4* u4 = (const float4*)(&sU[h][0]);
                float4 ua = u4[lane], ub = u4[lane + 32];
                part[h] = xa.x*ua.x + xa.y*ua.y + xa.z*ua.z + xa.w*ua.w
                        + xb.x*ub.x + xb.y*ub.y + xb.z*ub.z + xb.w*ub.w;
            }
        } else {
#pragma unroll
            for (int h = 0; h < HH; h++) part[h] = 0.f;
        }
#pragma unroll
        for (int h = 0; h < HH; h++) {
            float v = part[h];
#pragma unroll
            for (int off = 16; off > 0; off >>= 1)
                v += __shfl_xor_sync(0xffffffffu, v, off);
            if (lane == 0)
                d_logits[(eb*HH + h)*CAPC + slot] = (tok >= 0) ? v * scale : 0.f;
        }
    }
}

// ======== K4: softmax (redundant per group) + partial y for 32 slots, MLP-4 ========
__global__ void __launch_bounds__(256) k_y(const float* __restrict__ x) {
    __shared__ float satt[HH][CAPC];
    __shared__ int   stok[32];

    int ebg = blockIdx.x;
    int eb = ebg >> 3, grp = ebg & 7;
    int b = eb & 7;
    int tid = threadIdx.x, lane = tid & 31, warp = tid >> 5;

    if (tid < 32) stok[tid] = d_slot_tok[eb*CAPC + grp*32 + tid];
    {
        int h = warp;
        const float* row = d_logits + (eb*HH + h)*CAPC;
        float vals[8];
        float mx = -1e30f;
#pragma unroll
        for (int k = 0; k < 8; k++) { vals[k] = row[lane + 32*k]; mx = fmaxf(mx, vals[k]); }
#pragma unroll
        for (int off = 16; off > 0; off >>= 1)
            mx = fmaxf(mx, __shfl_xor_sync(0xffffffffu, mx, off));
        float s = 0.f;
#pragma unroll
        for (int k = 0; k < 8; k++) { vals[k] = expf(vals[k] - mx); s += vals[k]; }
#pragma unroll
        for (int off = 16; off > 0; off >>= 1)
            s += __shfl_xor_sync(0xffffffffu, s, off);
        float inv = 1.f / s;
#pragma unroll
        for (int k = 0; k < 8; k++) satt[h][lane + 32*k] = vals[k] * inv;
    }
    __syncthreads();

    // partial y over 32 slots, 4 loads in flight
    float yv[HH];
#pragma unroll
    for (int h = 0; h < HH; h++) yv[h] = 0.f;
#pragma unroll
    for (int c4 = 0; c4 < 8; c4++) {
        int c0 = grp*32 + c4*4;
        int t0 = stok[c4*4+0], t1 = stok[c4*4+1], t2 = stok[c4*4+2], t3 = stok[c4*4+3];
        float x0 = (t0 >= 0) ? x[((size_t)b*NN + t0)*DD + tid] : 0.f;
        float x1 = (t1 >= 0) ? x[((size_t)b*NN + t1)*DD + tid] : 0.f;
        float x2 = (t2 >= 0) ? x[((size_t)b*NN + t2)*DD + tid] : 0.f;
        float x3 = (t3 >= 0) ? x[((size_t)b*NN + t3)*DD + tid] : 0.f;
#pragma unroll
        for (int h = 0; h < HH; h++) {
            yv[h] += satt[h][c0+0] * x0 + satt[h][c0+1] * x1
                   + satt[h][c0+2] * x2 + satt[h][c0+3] * x3;
        }
    }
#pragma unroll
    for (int h = 0; h < HH; h++)
        d_py[((size_t)ebg*HH + h)*DD + tid] = yv[h];
}

// ==== K5: merge 8 partials + o-projection + sigmoid gate; 1024 threads ====
__global__ void __launch_bounds__(1024, 1) k_og(
    const float* __restrict__ Wkv, const float* __restrict__ Wp,
    const float* __restrict__ bp)
{
    __shared__ float sY[HH][DD];
    __shared__ float sO[DD];
    __shared__ float sRed[4][DD];

    int eb = blockIdx.x;
    int e = eb >> 3;
    int tid = threadIdx.x;
    int g = tid >> 8, wtid = tid & 255;

    for (int i = tid; i < HH*DD; i += 1024) {
        float acc = 0.f;
#pragma unroll
        for (int k = 0; k < NG; k++)
            acc += d_py[(size_t)(eb*NG + k)*2048 + i];
        ((float*)sY)[i] = acc;
    }
    __syncthreads();

    const float* Wkve = Wkv + (size_t)e*DD*2*DD;
    {
        int h = wtid >> 5;
        float acc = 0.f;
        int d0 = g*64;
#pragma unroll 4
        for (int d = d0; d < d0 + 64; d++)
            acc += sY[h][d] * Wkve[(size_t)d*512 + 256 + wtid];
        sRed[g][wtid] = acc;
    }
    __syncthreads();
    if (tid < DD)
        sO[tid] = sRed[0][tid] + sRed[1][tid] + sRed[2][tid] + sRed[3][tid];
    __syncthreads();

    {
        const float* Wpe = Wp + (size_t)e*DD*DD;
        float acc = 0.f;
        int j0 = g*64;
#pragma unroll 4
        for (int j = j0; j < j0 + 64; j++) acc += sO[j] * Wpe[j*DD + wtid];
        sRed[g][wtid] = acc;
    }
    __syncthreads();
    if (tid < DD) {
        float gsum = sRed[0][tid] + sRed[1][tid] + sRed[2][tid] + sRed[3][tid]
                   + bp[e*DD + tid];
        d_gates[eb*DD + tid] = 1.f / (1.f + expf(-gsum));
    }
}

// ============ K6: combine + loss (block 0) + counter reset ============
__global__ void __launch_bounds__(256) k_combine(
    const float* __restrict__ x, float* __restrict__ out, int out_size)
{
    __shared__ float red[128];
    int tid = threadIdx.x;
    int token = blockIdx.x*4 + (tid >> 6);
    int q = tid & 63;
    int b = token >> 11;
    int i1 = d_idx1[token], i2 = d_idx2[token];
    float w1 = d_g1[token], w2 = d_g2[token];
    float4 xv = ((const float4*)x)[(size_t)token*64 + q];
    float4 ga = ((const float4*)(d_gates + (i1*BB + b)*DD))[q];
    float4 gb = ((const float4*)(d_gates + (i2*BB + b)*DD))[q];
    float4 o;
    o.x = xv.x * (w1*ga.x + w2*gb.x);
    o.y = xv.y * (w1*ga.y + w2*gb.y);
    o.z = xv.z * (w1*ga.z + w2*gb.z);
    o.w = xv.w * (w1*ga.w + w2*gb.w);
    ((float4*)out)[(size_t)token*64 + q] = o;

    if (blockIdx.x == 0) {
        if (tid < 128) {
            red[tid] = d_probsum[tid] * (float)d_count1[tid];
            d_probsum[tid] = 0.f;          // reset for next (deterministic) run
            d_count1[tid] = 0;
        }
        __syncthreads();
        if (tid < 64) red[tid] += red[tid + 64];
        __syncthreads();
        if (tid < 32) {
            float v = red[tid] + red[tid + 32];
#pragma unroll
            for (int off = 16; off > 0; off >>= 1)
                v += __shfl_xor_sync(0xffffffffu, v, off);
            if (tid == 0 && out_size > NTOK*DD) {
                float coef = (float)(EE*EE) * 0.01f / ((float)NN * (float)NN * (float)(BB*EE));
                out[NTOK*DD] = v * coef;
            }
        }
    }
}

// ------------------------- launch -------------------------
extern "C" void kernel_launch(void* const* d_in, const int* in_sizes, int n_in,
                              void* d_out, int out_size) {
    const float* x     = (const float*)d_in[0];
    const float* audio = (const float*)d_in[1];
    const float* wg    = (const float*)d_in[2];
    const float* Wq    = (const float*)d_in[3];
    const float* Wkv   = (const float*)d_in[4];
    const float* Wp    = (const float*)d_in[5];
    const float* bp    = (const float*)d_in[6];
    float* out = (float*)d_out;

    k_gating<<<NTOK/8, 256>>>(x, wg);
    k_qU<<<EB, 1024>>>(audio, Wq, Wkv);
    k_poslog<<<EB*NG, 256>>>(x);
    k_y<<<EB*NG, 256>>>(x);
    k_og<<<EB, 1024>>>(Wkv, Wp, bp);
    k_combine<<<NTOK/4, 256>>>(x, out, out_size);
}